// round 2
// baseline (speedup 1.0000x reference)
#include <cuda_runtime.h>
#include <math.h>

#define D 32
#define NCOL 529          // 1 + 32 + 496

// ---- scratch (no allocations allowed) ----
__device__ float  g_acc[560];    // [0..527] upper-tri X^T X (incl diag), [528..559] column sums
__device__ float  g_stats[64];   // mean[32], inv_sd[32]
__device__ float4 g_pc[512];     // per (iter,lane): {A, B, C, packed(col | i<<16 | j<<21)}

__device__ __forceinline__ int tri_idx(int i, int j) {   // i <= j, upper triangle incl diag
    return i * 32 - (i * (i - 1)) / 2 + (j - i);
}

// ---------------- kernel 0: zero accumulators (graph replays must be deterministic) ------------
__global__ void zero_kernel() {
    int t = blockIdx.x * blockDim.x + threadIdx.x;
    if (t < 560) g_acc[t] = 0.0f;
}

// ---------------- kernel 1: column sums + upper-tri X^T X ----------------
__global__ void __launch_bounds__(256) train_kernel(const float* __restrict__ X, int n_train) {
    __shared__ float sx[128][33];   // +1 pad
    const int tid = threadIdx.x;

    // entry slots: e0 = tid (always), e1 = tid+256 (always < 560), e2 = tid+512 (tid < 48)
    int e0 = tid, e1 = tid + 256, e2 = tid + 512;
    bool has2 = (e2 < 560);

    int i0, j0, i1, j1, i2 = -1, j2 = -1;
    {
        int e = e0;
        if (e < 528) { int i = 0, rem = e; while (rem >= 32 - i) { rem -= 32 - i; i++; } i0 = i; j0 = i + rem; }
        else { i0 = -1; j0 = e - 528; }
        e = e1;
        if (e < 528) { int i = 0, rem = e; while (rem >= 32 - i) { rem -= 32 - i; i++; } i1 = i; j1 = i + rem; }
        else { i1 = -1; j1 = e - 528; }
        if (has2) {
            e = e2;
            if (e < 528) { int i = 0, rem = e; while (rem >= 32 - i) { rem -= 32 - i; i++; } i2 = i; j2 = i + rem; }
            else { i2 = -1; j2 = e - 528; }
        }
    }

    float a0 = 0.0f, a1 = 0.0f, a2 = 0.0f;
    int ntiles = (n_train + 127) / 128;
    for (int t = blockIdx.x; t < ntiles; t += gridDim.x) {
        int r0  = t * 128;
        int cnt = min(128, n_train - r0);
        for (int idx = tid; idx < cnt * 32; idx += 256)
            sx[idx >> 5][idx & 31] = X[r0 * 32 + idx];
        __syncthreads();

        if (i0 >= 0) { for (int r = 0; r < cnt; r++) a0 += sx[r][i0] * sx[r][j0]; }
        else         { for (int r = 0; r < cnt; r++) a0 += sx[r][j0]; }
        if (i1 >= 0) { for (int r = 0; r < cnt; r++) a1 += sx[r][i1] * sx[r][j1]; }
        else         { for (int r = 0; r < cnt; r++) a1 += sx[r][j1]; }
        if (has2) {
            if (i2 >= 0) { for (int r = 0; r < cnt; r++) a2 += sx[r][i2] * sx[r][j2]; }
            else         { for (int r = 0; r < cnt; r++) a2 += sx[r][j2]; }
        }
        __syncthreads();
    }
    atomicAdd(&g_acc[e0], a0);
    atomicAdd(&g_acc[e1], a1);
    if (has2) atomicAdd(&g_acc[e2], a2);
}

// ---------------- kernel 2: build stats + pair-constant table (1 block, 512 threads) ----------
__global__ void __launch_bounds__(512) prep_kernel(int n_train) {
    __shared__ float mean_s[32], isd_s[32];
    const int t  = threadIdx.x;
    const float fn = (float)n_train;

    if (t < 32) {
        float m   = g_acc[528 + t] / fn;
        float var = (g_acc[tri_idx(t, t)] - fn * m * m) / (fn - 1.0f);
        float isd = 1.0f / sqrtf(var);
        mean_s[t] = m;  isd_s[t] = isd;
        g_stats[t] = m; g_stats[32 + t] = isd;
    }
    __syncthreads();

    // Triangle-row packing: iter k<15 -> rows k (lanes 0..30-k) and 30-k (lanes 31-k..31);
    // iter 15 -> row 15 (lanes 0..15), lanes 16..31 inactive.
    int k = t >> 5, lane = t & 31;
    int i = -1, j = -1;
    if (k < 15) {
        if (lane <= 30 - k) { i = k;      j = k + 1 + lane; }
        else                { i = 30 - k; j = i + 1 + (lane - (31 - k)); }
    } else if (lane < 16)   { i = 15;     j = 16 + lane; }

    float4 pc;
    if (i >= 0) {
        float cij = (g_acc[tri_idx(i, j)] - fn * mean_s[i] * mean_s[j]) / (fn - 1.0f);
        float r   = cij * isd_s[i] * isd_s[j];
        float om  = 1.0f - r * r;
        float inv = 1.0f / om;
        pc.x = 0.5f * r * r * inv;      // A
        pc.y = -r * inv;                // B
        pc.z = sqrtf(om);               // C
        int p   = i * 31 - (i * (i - 1)) / 2 + (j - i - 1);   // combinations() order
        int col = 33 + p;
        pc.w = __int_as_float(col | (i << 16) | (j << 21));
    } else {
        pc.x = pc.y = pc.z = 0.0f;
        pc.w = __int_as_float(-1);
    }
    g_pc[t] = pc;
}

// ---------------- kernel 3: eval — one warp per point, z register-resident --------------------
__global__ void __launch_bounds__(256) eval_kernel(const float* __restrict__ x,
                                                   float* __restrict__ out, int n_eval) {
    __shared__ float4 pc[512];
    __shared__ float  st[64];
    const int tid = threadIdx.x;
    pc[tid]       = g_pc[tid];
    pc[tid + 256] = g_pc[tid + 256];
    if (tid < 64) st[tid] = g_stats[tid];
    __syncthreads();

    const int lane  = tid & 31;
    const int point = blockIdx.x * 8 + (tid >> 5);
    if (point >= n_eval) return;   // warp-uniform exit

    float xv = x[point * 32 + lane];
    float z  = (xv - st[lane]) * st[32 + lane];

    float* o = out + (size_t)point * NCOL;
    o[lane] = 1.0f;                // null + singleton columns are all-ones
    if (lane == 0) o[32] = 1.0f;

#pragma unroll
    for (int k = 0; k < 16; k++) {
        float4 c = pc[k * 32 + lane];
        int w    = __float_as_int(c.w);
        float zi = __shfl_sync(0xffffffffu, z, (w >> 16) & 31);
        float zj = __shfl_sync(0xffffffffu, z, (w >> 21) & 31);
        float s  = zi * zi + zj * zj;
        float tt = fmaf(c.x, s, c.y * (zi * zj));
        float v  = c.z * __expf(tt);
        if (w >= 0) o[w & 0xFFFF] = v;
    }
}

// ---------------- launcher ----------------
extern "C" void kernel_launch(void* const* d_in, const int* in_sizes, int n_in,
                              void* d_out, int out_size) {
    const float* X_train = (const float*)d_in[0];
    const float* x       = (const float*)d_in[1];
    float*       out     = (float*)d_out;

    int n_train = in_sizes[0] / D;
    int n_eval  = in_sizes[1] / D;

    zero_kernel<<<3, 256>>>();
    train_kernel<<<128, 256>>>(X_train, n_train);
    prep_kernel<<<1, 512>>>(n_train);
    eval_kernel<<<(n_eval + 7) / 8, 256>>>(x, out, n_eval);
}